// round 8
// baseline (speedup 1.0000x reference)
#include <cuda_runtime.h>
#include <cuda_bf16.h>
#include <math.h>
#include <stdint.h>

// Problem constants
#define Bq   8
#define Sq   2048
#define Dq   256
#define Hq   4
#define Dh   64
#define Mq   (Bq * Sq)        // 16384 rows

// ---------------- scratch (device globals; no allocation allowed) ----------
__device__ float g_q  [Bq * Hq * Sq * Dh];    // [B,H,S,Dh]
__device__ float g_k  [Bq * Hq * Sq * Dh];    // [B,H,S,Dh]
__device__ float g_v  [Bq * Hq * Dh * Sq];    // [B,H,Dh,S]  (transposed!)
__device__ float g_ctx[Mq * Dq];              // [B,S,D]
__device__ float g_msg[Mq * Dq];
__device__ float g_y  [Mq * 2 * Dq];

// =====================  helpers ============================================
__device__ __forceinline__ uint32_t smem_u32(const void* p) {
    uint32_t a;
    asm("{ .reg .u64 t; cvta.to.shared.u64 t, %1; cvt.u32.u64 %0, t; }"
        : "=r"(a) : "l"(p));
    return a;
}
__device__ __forceinline__ void cp_async16(uint32_t saddr, const void* gaddr) {
    asm volatile("cp.async.cg.shared.global [%0], [%1], 16;\n"
                 :: "r"(saddr), "l"(gaddr));
}
#define CP_COMMIT() asm volatile("cp.async.commit_group;" ::: "memory")
#define CP_WAIT0()  asm volatile("cp.async.wait_group 0;" ::: "memory")
#define CP_WAIT1()  asm volatile("cp.async.wait_group 1;" ::: "memory")

// m16n8k8 tf32 mma: D = A*B + D (fp32 accum). Raw fp32 bits as tf32.
__device__ __forceinline__ void mma_tf32(float* d, const uint32_t* a, const uint32_t* b) {
    asm volatile(
        "mma.sync.aligned.m16n8k8.row.col.f32.tf32.tf32.f32 "
        "{%0,%1,%2,%3}, {%4,%5,%6,%7}, {%8,%9}, {%0,%1,%2,%3};"
        : "+f"(d[0]), "+f"(d[1]), "+f"(d[2]), "+f"(d[3])
        : "r"(a[0]), "r"(a[1]), "r"(a[2]), "r"(a[3]),
          "r"(b[0]), "r"(b[1]));
}

// ldmatrix x4: four 8x8 b16 tiles == full tf32 A-frag or two tf32 B-frags.
__device__ __forceinline__ void ldsm_x4(uint32_t* r, uint32_t addr) {
    asm volatile("ldmatrix.sync.aligned.m8n8.x4.shared.b16 {%0,%1,%2,%3}, [%4];"
                 : "=r"(r[0]), "=r"(r[1]), "=r"(r[2]), "=r"(r[3]) : "r"(addr));
}

// ================  shared GEMM tile config =================================
// CTA tile 128x128, 8 warps (4m x 2n), warp tile 32x64, 2-stage cp.async.
#define TS        36
#define STAGE_F   (128 * TS)
#define G_STAGE_B (2 * STAGE_F * 4)
#define G_STAGES  2
#define G_SMEM_TOT (G_STAGES * G_STAGE_B)

// ---- per-thread ldmatrix byte-offsets within a stage ----------------------
// A-frag (x4): lanes 0-7: rows r0..r0+7 @k0 | 8-15: rows+8 @k0
//              16-23: rows @k0+4 | 24-31: rows+8 @k0+4
// B-frags (x4, two n-cols-of-8): lanes 0-7: n0..7 @k0 | 8-15: n0..7 @k0+4
//              16-23: n8..15 @k0 | 24-31: n8..15 @k0+4
struct LdsmOffs {
    uint32_t a0, a1;    // A matrices for mt=0,1 (relative to stage base)
    uint32_t b[4];      // B matrices for nt pairs p=0..3 (incl. STAGE_F)
};
__device__ __forceinline__ LdsmOffs make_offs(int lane, int wm, int wn) {
    LdsmOffs o;
    const int la   = lane & 15;
    const int asel = (lane >> 4) * 4;
    o.a0 = (uint32_t)(((wm +      la) * TS + asel) * 4);
    o.a1 = (uint32_t)(((wm + 16 + la) * TS + asel) * 4);
    const int lb   = (lane & 7) + ((lane >> 4) << 3);
    const int bsel = ((lane >> 3) & 1) * 4;
#pragma unroll
    for (int p = 0; p < 4; p++)
        o.b[p] = (uint32_t)((STAGE_F + (wn + p * 16 + lb) * TS + bsel) * 4);
    return o;
}

// ================  generic GEMM: C = A[M,K] @ W[N,K]^T + bias (+res) =======
// If A2 != null, A covers k<256 and A2 covers k>=256 (both row-stride 256).
template <bool RES>
__global__ void __launch_bounds__(256)
mma_gemm_kernel(const float* __restrict__ A, const float* __restrict__ A2,
                const float* __restrict__ W,
                const float* __restrict__ bias, const float* __restrict__ resid,
                float* __restrict__ C, int M, int N, int K, int lda) {
    extern __shared__ __align__(16) float sm[];
    const uint32_t sb = smem_u32(sm);
    const int tid  = threadIdx.x;
    const int wid  = tid >> 5;
    const int lane = tid & 31;
    const int g    = lane >> 2;
    const int t4   = lane & 3;
    const int bm = blockIdx.y * 128;
    const int bn = blockIdx.x * 128;
    const int wm = (wid & 3) * 32;
    const int wn = (wid >> 2) * 64;
    const int NT = K >> 5;
    const LdsmOffs offs = make_offs(lane, wm, wn);

    float acc[2][8][4];
#pragma unroll
    for (int i = 0; i < 2; i++)
#pragma unroll
        for (int j = 0; j < 8; j++)
#pragma unroll
            for (int c = 0; c < 4; c++) acc[i][j][c] = 0.f;

    auto ldstage = [&](int u) {
        const int slot = u & 1;
        const int k0 = u << 5;
        const float* srcA = A;
        int ka = k0;
        if (A2 != nullptr && k0 >= 256) { srcA = A2; ka = k0 - 256; }
        const uint32_t sbase = sb + (uint32_t)slot * G_STAGE_B;
#pragma unroll
        for (int i = 0; i < 4; i++) {
            const int idx = tid + i * 256;
            const int row = idx >> 3;
            const int ch  = idx & 7;
            cp_async16(sbase + (uint32_t)(row * TS + ch * 4) * 4,
                       srcA + (size_t)(bm + row) * lda + ka + ch * 4);
        }
#pragma unroll
        for (int i = 0; i < 4; i++) {
            const int idx = tid + i * 256;
            const int row = idx >> 3;
            const int ch  = idx & 7;
            cp_async16(sbase + (uint32_t)(STAGE_F + row * TS + ch * 4) * 4,
                       W + (size_t)(bn + row) * K + k0 + ch * 4);
        }
    };

    ldstage(0); CP_COMMIT();
    ldstage(1); CP_COMMIT();

    for (int t = 0; t < NT; t++) {
        CP_WAIT1();
        __syncthreads();

        const uint32_t sbase = sb + (uint32_t)(t & 1) * G_STAGE_B;
#pragma unroll
        for (int kc = 0; kc < 4; kc++) {
            const uint32_t kbyte = kc * 32;
            uint32_t af0[4], af1[4];
            ldsm_x4(af0, sbase + offs.a0 + kbyte);
            ldsm_x4(af1, sbase + offs.a1 + kbyte);
#pragma unroll
            for (int p = 0; p < 4; p++) {
                uint32_t b4[4];
                ldsm_x4(b4, sbase + offs.b[p] + kbyte);
                mma_tf32(acc[0][2 * p],     af0, b4);
                mma_tf32(acc[1][2 * p],     af1, b4);
                mma_tf32(acc[0][2 * p + 1], af0, b4 + 2);
                mma_tf32(acc[1][2 * p + 1], af1, b4 + 2);
            }
        }
        __syncthreads();
        if (t + 2 < NT) ldstage(t + 2);
        CP_COMMIT();
    }

#pragma unroll
    for (int nt = 0; nt < 8; nt++) {
        const int col = bn + wn + nt * 8 + t4 * 2;
        const float2 bv = *(const float2*)&bias[col];
#pragma unroll
        for (int mt = 0; mt < 2; mt++) {
            const int r0 = bm + wm + mt * 16 + g;
            float2 v0 = make_float2(acc[mt][nt][0] + bv.x, acc[mt][nt][1] + bv.y);
            float2 v1 = make_float2(acc[mt][nt][2] + bv.x, acc[mt][nt][3] + bv.y);
            if (RES) {
                const float2 r0v = *(const float2*)&resid[(size_t)r0 * N + col];
                const float2 r1v = *(const float2*)&resid[(size_t)(r0 + 8) * N + col];
                v0.x += r0v.x; v0.y += r0v.y;
                v1.x += r1v.x; v1.y += r1v.y;
            }
            *(float2*)&C[(size_t)r0 * N + col]       = v0;
            *(float2*)&C[(size_t)(r0 + 8) * N + col] = v1;
        }
    }
}

// ================  QKV GEMM + fused RoPE + split ===========================
// Canonical output col n' in [0,768): t=n'>>8 (0=q,1=k,2=v), h=(n'>>6)&3,
// d=n'&63. W rows permuted at load: src = h*192 + d*3 + t.
// q/k: RoPE'd, [B,H,S,Dh]; v: transposed store [B,H,Dh,S].
__global__ void __launch_bounds__(256)
qkv_gemm_rope_kernel(const float* __restrict__ A, const float* __restrict__ W,
                     const float* __restrict__ bias, const float* __restrict__ kp) {
    extern __shared__ __align__(16) float sm[];
    const uint32_t sb = smem_u32(sm);
    const int tid  = threadIdx.x;
    const int wid  = tid >> 5;
    const int lane = tid & 31;
    const int g    = lane >> 2;
    const int t4   = lane & 3;
    const int bm = blockIdx.y * 128;
    const int bn = blockIdx.x * 128;
    const int wm = (wid & 3) * 32;
    const int wn = (wid >> 2) * 64;
    const int NT = 8;                       // K = 256
    const LdsmOffs offs = make_offs(lane, wm, wn);

    float acc[2][8][4];
#pragma unroll
    for (int i = 0; i < 2; i++)
#pragma unroll
        for (int j = 0; j < 8; j++)
#pragma unroll
            for (int c = 0; c < 4; c++) acc[i][j][c] = 0.f;

    auto ldstage = [&](int u) {
        const int slot = u & 1;
        const int k0 = u << 5;
        const uint32_t sbase = sb + (uint32_t)slot * G_STAGE_B;
#pragma unroll
        for (int i = 0; i < 4; i++) {
            const int idx = tid + i * 256;
            const int row = idx >> 3;
            const int ch  = idx & 7;
            cp_async16(sbase + (uint32_t)(row * TS + ch * 4) * 4,
                       A + (size_t)(bm + row) * 256 + k0 + ch * 4);
        }
#pragma unroll
        for (int i = 0; i < 4; i++) {
            const int idx = tid + i * 256;
            const int row = idx >> 3;
            const int ch  = idx & 7;
            const int rp  = bn + row;              // canonical col
            const int tt  = rp >> 8;
            const int hh  = (rp >> 6) & 3;
            const int dd  = rp & 63;
            const int src = hh * 192 + dd * 3 + tt;
            cp_async16(sbase + (uint32_t)(STAGE_F + row * TS + ch * 4) * 4,
                       W + (size_t)src * 256 + k0 + ch * 4);
        }
    };

    ldstage(0); CP_COMMIT();
    ldstage(1); CP_COMMIT();

    for (int t = 0; t < NT; t++) {
        CP_WAIT1();
        __syncthreads();

        const uint32_t sbase = sb + (uint32_t)(t & 1) * G_STAGE_B;
#pragma unroll
        for (int kc = 0; kc < 4; kc++) {
            const uint32_t kbyte = kc * 32;
            uint32_t af0[4], af1[4];
            ldsm_x4(af0, sbase + offs.a0 + kbyte);
            ldsm_x4(af1, sbase + offs.a1 + kbyte);
#pragma unroll
            for (int p = 0; p < 4; p++) {
                uint32_t b4[4];
                ldsm_x4(b4, sbase + offs.b[p] + kbyte);
                mma_tf32(acc[0][2 * p],     af0, b4);
                mma_tf32(acc[1][2 * p],     af1, b4);
                mma_tf32(acc[0][2 * p + 1], af0, b4 + 2);
                mma_tf32(acc[1][2 * p + 1], af1, b4 + 2);
            }
        }
        __syncthreads();
        if (t + 2 < NT) ldstage(t + 2);
        CP_COMMIT();
    }

    // ---- epilogue: bias + RoPE + scatter -----------------------------------
    const int type = bn >> 8;               // 0=q, 1=k, 2=v (uniform per CTA)
    const float qs = (type == 0) ? 0.125f : 1.0f;

#pragma unroll
    for (int nt = 0; nt < 8; nt++) {
        const int colp = bn + wn + nt * 8 + t4 * 2;   // canonical col (even)
        const int h = (colp >> 6) & 3;
        const int d = colp & 63;
        const float b0 = bias[h * 192 + d * 3 + type];
        const float b1 = bias[h * 192 + (d + 1) * 3 + type];
#pragma unroll
        for (int mt = 0; mt < 2; mt++) {
            const int mA = bm + wm + mt * 16 + g;
#pragma unroll
            for (int rr = 0; rr < 2; rr++) {
                const int m = mA + rr * 8;
                const float x0 = acc[mt][nt][rr * 2 + 0] + b0;
                const float x1 = acc[mt][nt][rr * 2 + 1] + b1;
                const int bb = m >> 11;
                const int ss = m & 2047;
                if (type == 2) {
                    // transposed V store: [B,H,Dh,S]
                    const size_t off = (((size_t)(bb * 4 + h)) * 64 + d) * 2048 + ss;
                    g_v[off]        = x0;
                    g_v[off + 2048] = x1;
                } else {
                    const float2 c2 = *(const float2*)&kp[(size_t)m * 64 + d];
                    const float2 s2 = *(const float2*)&kp[(size_t)Mq * 64 + (size_t)m * 64 + d];
                    const float o0 = (x0 * c2.x - x1 * s2.x) * qs;
                    const float o1 = (x1 * c2.y + x0 * s2.y) * qs;
                    float* dst = (type == 0) ? g_q : g_k;
                    const size_t off = (((size_t)(bb * 4 + h)) * 2048 + ss) * 64 + d;
                    *(float2*)&dst[off] = make_float2(o0, o1);
                }
            }
        }
    }
}

// ============== flash attention with m16n8k8 tf32 mma + ldmatrix ===========
// Q,K: [B,H,S,64]; V: [B,H,64,S] (d-major). ctx: [B,S,256].
#define ATT_KPAD 68
#define ATT_VPAD 68
#define ATT_KSTG (64 * ATT_KPAD)
#define ATT_VSTG (64 * ATT_VPAD)
#define ATT_SMEM ((2 * ATT_KSTG + 2 * ATT_VSTG) * 4)

__global__ void __launch_bounds__(256)
fa_mma_kernel(const float* __restrict__ Q, const float* __restrict__ K,
              const float* __restrict__ V, float* __restrict__ ctx) {
    extern __shared__ __align__(16) float sm[];
    float* Ks = sm;
    float* Vs = sm + 2 * ATT_KSTG;
    const uint32_t sKu = smem_u32(Ks);
    const uint32_t sVu = smem_u32(Vs);

    const int tid = threadIdx.x, wid = tid >> 5, lane = tid & 31;
    const int g = lane >> 2, t4 = lane & 3;
    const int b = blockIdx.z, h = blockIdx.y, it = blockIdx.x;
    const size_t base = ((size_t)(b * Hq + h)) * Sq * Dh;

    // ldmatrix per-thread offsets (B-frag pattern) for K and V tiles
    const int lb   = (lane & 7) + ((lane >> 4) << 3);
    const int bsel = ((lane >> 3) & 1) * 4;
    uint32_t kmoff[4], vmoff[4];
#pragma unroll
    for (int p = 0; p < 4; p++) {
        kmoff[p] = (uint32_t)(((p * 16 + lb) * ATT_KPAD + bsel) * 4);
        vmoff[p] = (uint32_t)(((p * 16 + lb) * ATT_VPAD + bsel) * 4);
    }

    // ---- stage Q tile (128x64) into K region --------------------------------
    {
        const float* Qg = Q + base + (size_t)it * 128 * Dh;
#pragma unroll
        for (int i = 0; i < 8; i++) {
            const int idx = tid + i * 256;
            const int row = idx >> 4;
            const int ch  = idx & 15;
            cp_async16(sKu + (uint32_t)(row * ATT_KPAD + ch * 4) * 4,
                       Qg + row * 64 + ch * 4);
        }
    }
    CP_COMMIT(); CP_WAIT0();
    __syncthreads();

    // Q A-frags via ldmatrix: rows wid*16 + (lane&15), k-half (lane>>4)*4
    uint32_t aq[8][4];
    {
        const uint32_t qoff = (uint32_t)(((wid * 16 + (lane & 15)) * ATT_KPAD
                                          + (lane >> 4) * 4) * 4);
#pragma unroll
        for (int kb = 0; kb < 8; kb++)
            ldsm_x4(aq[kb], sKu + qoff + kb * 32);
    }
    __syncthreads();

    const float* Kg = K + base;
    const float* Vg = V + base;    // [64][2048]
    auto ldkv = [&](int jt) {
        const int slot = jt & 1;
#pragma unroll
        for (int i = 0; i < 4; i++) {
            const int idx = tid + i * 256;
            const int row = idx >> 4;
            const int ch  = idx & 15;
            cp_async16(sKu + (uint32_t)(slot * ATT_KSTG + row * ATT_KPAD + ch * 4) * 4,
                       Kg + (size_t)(jt * 64 + row) * 64 + ch * 4);
            cp_async16(sVu + (uint32_t)(slot * ATT_VSTG + row * ATT_VPAD + ch * 4) * 4,
                       Vg + (size_t)row * Sq + jt * 64 + ch * 4);
        }
    };

    ldkv(0); CP_COMMIT();

    float m0 = -INFINITY, m1 = -INFINITY, l0 = 0.f, l1 = 0.f;
    float o[8][4];
#pragma unroll
    for (int nt = 0; nt < 8; nt++)
#pragma unroll
        for (int c = 0; c < 4; c++) o[nt][c] = 0.f;

    for (int jt = 0; jt < Sq / 64; jt++) {
        if (jt + 1 < Sq / 64) { ldkv(jt + 1); CP_COMMIT(); CP_WAIT1(); }
        else                  { CP_WAIT0(); }
        __syncthreads();

        const uint32_t kbase = sKu + (uint32_t)((jt & 1) * ATT_KSTG) * 4;
        const uint32_t vbase = sVu + (uint32_t)((jt & 1) * ATT_VSTG) * 4;

        // ---- S = Q K^T -----------------------------------------------------
        float sc[8][4];
#pragma unroll
        for (int nt = 0; nt < 8; nt++)
#pragma unroll
            for (int c = 0; c < 4; c++) sc[nt][c] = 0.f;
#pragma unroll
        for (int kb = 0; kb < 8; kb++) {
            const uint32_t kbyte = kb * 32;
#pragma unroll
            for (int p = 0; p < 4; p++) {
                uint32_t b4[4];
                ldsm_x4(b4, kbase + kmoff[p] + kbyte);
                mma_tf32(sc[2 * p],     aq[kb], b4);
                mma_tf32(sc[2 * p + 1], aq[kb], b4 + 2);
            }
        }

        // ---- online softmax ------------------------------------------------
        float mx0 = -INFINITY, mx1 = -INFINITY;
#pragma unroll
        for (int nt = 0; nt < 8; nt++) {
            mx0 = fmaxf(mx0, fmaxf(sc[nt][0], sc[nt][1]));
            mx1 = fmaxf(mx1, fmaxf(sc[nt][2], sc[nt][3]));
        }
        mx0 = fmaxf(mx0, __shfl_xor_sync(0xffffffffu, mx0, 1));
        mx0 = fmaxf(mx0, __shfl_xor_sync(0xffffffffu, mx0, 2));
        mx1 = fmaxf(mx1, __shfl_xor_sync(0xffffffffu, mx1, 1));
        mx1 = fmaxf(mx1, __shfl_xor_sync(0xffffffffu, mx1, 2));

        const float nm0 = fmaxf(m0, mx0);
        const float nm1 = fmaxf(m1, mx1);
        const float f0 = __expf(m0 - nm0);
        const float f1 = __expf(m1 - nm1);
        float sum0 = 0.f, sum1 = 0.f;
#pragma unroll
        for (int nt = 0; nt < 8; nt++) {
            sc[nt][0] = __expf(sc[nt][0] - nm0);
            sc[nt][1] = __expf(sc[nt][1] - nm0);
            sc[nt][2] = __expf(sc[nt][2] - nm1);
            sc[nt][3] = __expf(sc[nt][3] - nm1);
            sum0 += sc[nt][0] + sc[nt][1];
            sum1 += sc[nt][2] + sc[nt][3];
        }
        sum0 += __shfl_xor_sync(0xffffffffu, sum0, 1);
        sum0 += __shfl_xor_sync(0xffffffffu, sum0, 2);
        sum1 += __shfl_xor_sync(0xffffffffu, sum1, 1);
        sum1 += __shfl_xor_sync(0xffffffffu, sum1, 2);
        l0 = l0 * f0 + sum0;
        l1 = l1 * f1 + sum1;
        m0 = nm0; m1 = nm1;
#pragma unroll
        for (int nt = 0; nt < 8; nt++) {
            o[nt][0] *= f0; o[nt][1] *= f0;
            o[nt][2] *= f1; o[nt][3] *= f1;
        }

        // ---- O += P V  (P C-frag -> A-frag shuffles; V via ldmatrix) -------
        const int qbase = lane & ~3;
        const int src0 = qbase + (t4 >> 1);
        const int src1 = src0 + 2;
        const bool odd = (t4 & 1);
#pragma unroll
        for (int kb = 0; kb < 8; kb++) {
            float s00 = __shfl_sync(0xffffffffu, sc[kb][0], src0);
            float s01 = __shfl_sync(0xffffffffu, sc[kb][1], src0);
            float s02 = __shfl_sync(0xffffffffu, sc[kb][2], src0);
            float s03 = __shfl_sync(0xffffffffu, sc[kb][3], src0);
            float s10 = __shfl_sync(0xffffffffu, sc[kb][0], src1);
            float s11 = __shfl_sync(0xffffffffu, sc[kb][1], src1);
            float s12 = __shfl_sync(0xffffffffu, sc[kb][2], src1);
            float s13 = __shfl_sync(0xffffffffu, sc[kb][3], src1);
            uint32_t ap[4];
            ap[0] = __float_as_uint(odd ? s01 : s00);
            ap[1] = __float_as_uint(odd ? s03 : s02);
            ap[2] = __float_as_uint(odd ? s11 : s10);
            ap[3] = __float_as_uint(odd ? s13 : s12);
            const uint32_t jbyte = kb * 32;
#pragma unroll
            for (int p = 0; p < 4; p++) {
                uint32_t b4[4];
                ldsm_x4(b4, vbase + vmoff[p] + jbyte);
                mma_tf32(o[2 * p],     ap, b4);
                mma_tf32(o[2 * p + 1], ap, b4 + 2);
            }
        }
        __syncthreads();
    }

    const float il0 = 1.f / l0;
    const float il1 = 1.f / l1;
    const int row0 = it * 128 + wid * 16 + g;
#pragma unroll
    for (int nt = 0; nt < 8; nt++) {
        const int col = h * Dh + nt * 8 + t4 * 2;
        float2 v0 = make_float2(o[nt][0] * il0, o[nt][1] * il0);
        float2 v1 = make_float2(o[nt][2] * il1, o[nt][3] * il1);
        *(float2*)&ctx[((size_t)b * Sq + row0) * Dq + col]     = v0;
        *(float2*)&ctx[((size_t)b * Sq + row0 + 8) * Dq + col] = v1;
    }
}

// ---------------- LayerNorm(512) + exact GELU, warp per row ----------------
__global__ void __launch_bounds__(256)
ln_gelu_kernel(const float* __restrict__ gamma, const float* __restrict__ beta) {
    const int lane = threadIdx.x & 31;
    const int row  = blockIdx.x * 8 + (threadIdx.x >> 5);
    float* rp = g_y + (size_t)row * 512;

    float4 x[4];
    float s = 0.f, ss = 0.f;
#pragma unroll
    for (int j = 0; j < 4; j++) {
        x[j] = *(const float4*)&rp[lane * 4 + j * 128];
        s  += x[j].x + x[j].y + x[j].z + x[j].w;
        ss += x[j].x * x[j].x + x[j].y * x[j].y + x[j].z * x[j].z + x[j].w * x[j].w;
    }
#pragma unroll
    for (int msk = 16; msk >= 1; msk >>= 1) {
        s  += __shfl_xor_sync(0xffffffffu, s,  msk);
        ss += __shfl_xor_sync(0xffffffffu, ss, msk);
    }
    const float mu  = s * (1.f / 512.f);
    const float var = ss * (1.f / 512.f) - mu * mu;
    const float inv = rsqrtf(var + 1e-5f);

#pragma unroll
    for (int j = 0; j < 4; j++) {
        const int c = lane * 4 + j * 128;
        const float4 gm = *(const float4*)&gamma[c];
        const float4 bt = *(const float4*)&beta[c];
        float4 y;
        y.x = (x[j].x - mu) * inv * gm.x + bt.x;
        y.y = (x[j].y - mu) * inv * gm.y + bt.y;
        y.z = (x[j].z - mu) * inv * gm.z + bt.z;
        y.w = (x[j].w - mu) * inv * gm.w + bt.w;
        y.x = 0.5f * y.x * (1.f + erff(y.x * 0.70710678118654752440f));
        y.y = 0.5f * y.y * (1.f + erff(y.y * 0.70710678118654752440f));
        y.z = 0.5f * y.z * (1.f + erff(y.z * 0.70710678118654752440f));
        y.w = 0.5f * y.w * (1.f + erff(y.w * 0.70710678118654752440f));
        *(float4*)&rp[c] = y;
    }
}

// ---------------- launch ----------------------------------------------------
extern "C" void kernel_launch(void* const* d_in, const int* in_sizes, int n_in,
                              void* d_out, int out_size) {
    const float* desc   = (const float*)d_in[0];
    const float* kp     = (const float*)d_in[1];
    const float* Wqkv_w = (const float*)d_in[2];
    const float* Wqkv_b = (const float*)d_in[3];
    const float* Wo_w   = (const float*)d_in[4];
    const float* Wo_b   = (const float*)d_in[5];
    const float* W1_w   = (const float*)d_in[6];
    const float* W1_b   = (const float*)d_in[7];
    const float* ln_g   = (const float*)d_in[8];
    const float* ln_b   = (const float*)d_in[9];
    const float* W2_w   = (const float*)d_in[10];
    const float* W2_b   = (const float*)d_in[11];
    float* out = (float*)d_out;

    void *p_q, *p_k, *p_v, *p_ctx, *p_msg, *p_y;
    cudaGetSymbolAddress(&p_q,   g_q);
    cudaGetSymbolAddress(&p_k,   g_k);
    cudaGetSymbolAddress(&p_v,   g_v);
    cudaGetSymbolAddress(&p_ctx, g_ctx);
    cudaGetSymbolAddress(&p_msg, g_msg);
    cudaGetSymbolAddress(&p_y,   g_y);

    cudaFuncSetAttribute(qkv_gemm_rope_kernel,
                         cudaFuncAttributeMaxDynamicSharedMemorySize, G_SMEM_TOT);
    cudaFuncSetAttribute(mma_gemm_kernel<false>,
                         cudaFuncAttributeMaxDynamicSharedMemorySize, G_SMEM_TOT);
    cudaFuncSetAttribute(mma_gemm_kernel<true>,
                         cudaFuncAttributeMaxDynamicSharedMemorySize, G_SMEM_TOT);
    cudaFuncSetAttribute(fa_mma_kernel,
                         cudaFuncAttributeMaxDynamicSharedMemorySize, ATT_SMEM);

    // 1) QKV GEMM + RoPE + split -> g_q/g_k (S-major), g_v (Dh-major)
    qkv_gemm_rope_kernel<<<dim3(6, Mq / 128), 256, G_SMEM_TOT>>>(
        desc, Wqkv_w, Wqkv_b, kp);

    // 2) flash attention (tensor-core, ldmatrix) -> ctx [B,S,D]
    fa_mma_kernel<<<dim3(Sq / 128, Hq, Bq), 256, ATT_SMEM>>>(
        (const float*)p_q, (const float*)p_k, (const float*)p_v, (float*)p_ctx);

    // 3) message = ctx @ Wo^T + b
    mma_gemm_kernel<false><<<dim3(Dq / 128, Mq / 128), 256, G_SMEM_TOT>>>(
        (const float*)p_ctx, nullptr, Wo_w, Wo_b, nullptr,
        (float*)p_msg, Mq, Dq, Dq, Dq);

    // 4) y = [desc | msg] @ W1^T + b   (virtual concat via split-K loader)
    mma_gemm_kernel<false><<<dim3(512 / 128, Mq / 128), 256, G_SMEM_TOT>>>(
        desc, (const float*)p_msg, W1_w, W1_b, nullptr,
        (float*)p_y, Mq, 512, 512, 256);

    // 5) LayerNorm + GELU (in place, warp per row)
    ln_gelu_kernel<<<Mq / 8, 256>>>(ln_g, ln_b);

    // 6) out = desc + y @ W2^T + b
    mma_gemm_kernel<true><<<dim3(Dq / 128, Mq / 128), 256, G_SMEM_TOT>>>(
        (const float*)p_y, nullptr, W2_w, W2_b, desc, out, Mq, Dq, 512, 512);
}

// round 10
// speedup vs baseline: 1.0875x; 1.0875x over previous
#include <cuda_runtime.h>
#include <cuda_bf16.h>
#include <math.h>
#include <stdint.h>

// Problem constants
#define Bq   8
#define Sq   2048
#define Dq   256
#define Hq   4
#define Dh   64
#define Mq   (Bq * Sq)        // 16384 rows

// ---------------- scratch (device globals; no allocation allowed) ----------
__device__ float g_q  [Bq * Hq * Sq * Dh];    // [B,H,S,Dh]
__device__ float g_k  [Bq * Hq * Sq * Dh];    // [B,H,S,Dh]
__device__ float g_v  [Bq * Hq * Dh * Sq];    // [B,H,Dh,S]  (transposed!)
__device__ float g_ctx[Mq * Dq];              // [B,S,D]
__device__ float g_msg[Mq * Dq];
__device__ float g_y  [Mq * 2 * Dq];

// =====================  helpers ============================================
__device__ __forceinline__ uint32_t smem_u32(const void* p) {
    uint32_t a;
    asm("{ .reg .u64 t; cvta.to.shared.u64 t, %1; cvt.u32.u64 %0, t; }"
        : "=r"(a) : "l"(p));
    return a;
}
__device__ __forceinline__ void cp_async16(uint32_t saddr, const void* gaddr) {
    asm volatile("cp.async.cg.shared.global [%0], [%1], 16;\n"
                 :: "r"(saddr), "l"(gaddr));
}
#define CP_COMMIT() asm volatile("cp.async.commit_group;" ::: "memory")
#define CP_WAIT0()  asm volatile("cp.async.wait_group 0;" ::: "memory")
#define CP_WAIT1()  asm volatile("cp.async.wait_group 1;" ::: "memory")

// m16n8k8 tf32 mma: D = A*B + D (fp32 accum). Raw fp32 bits as tf32.
__device__ __forceinline__ void mma_tf32(float* d, const uint32_t* a, const uint32_t* b) {
    asm volatile(
        "mma.sync.aligned.m16n8k8.row.col.f32.tf32.tf32.f32 "
        "{%0,%1,%2,%3}, {%4,%5,%6,%7}, {%8,%9}, {%0,%1,%2,%3};"
        : "+f"(d[0]), "+f"(d[1]), "+f"(d[2]), "+f"(d[3])
        : "r"(a[0]), "r"(a[1]), "r"(a[2]), "r"(a[3]),
          "r"(b[0]), "r"(b[1]));
}

// ldmatrix x4: four 8x8 b16 tiles == full tf32 A-frag or two tf32 B-frags.
__device__ __forceinline__ void ldsm_x4(uint32_t* r, uint32_t addr) {
    asm volatile("ldmatrix.sync.aligned.m8n8.x4.shared.b16 {%0,%1,%2,%3}, [%4];"
                 : "=r"(r[0]), "=r"(r[1]), "=r"(r[2]), "=r"(r[3]) : "r"(addr));
}

// ================  shared GEMM tile config =================================
// CTA tile 128x128, 8 warps (4m x 2n), warp tile 32x64, 3-stage cp.async.
#define TS        36
#define STAGE_F   (128 * TS)
#define G_STAGE_B (2 * STAGE_F * 4)
#define G_STAGES  3
#define G_SMEM_TOT (G_STAGES * G_STAGE_B)

// ---- per-thread ldmatrix byte-offsets within a stage ----------------------
struct LdsmOffs {
    uint32_t a0, a1;    // A matrices for mt=0,1 (relative to stage base)
    uint32_t b[4];      // B matrices for nt pairs p=0..3 (incl. STAGE_F)
};
__device__ __forceinline__ LdsmOffs make_offs(int lane, int wm, int wn) {
    LdsmOffs o;
    const int la   = lane & 15;
    const int asel = (lane >> 4) * 4;
    o.a0 = (uint32_t)(((wm +      la) * TS + asel) * 4);
    o.a1 = (uint32_t)(((wm + 16 + la) * TS + asel) * 4);
    const int lb   = (lane & 7) + ((lane >> 4) << 3);
    const int bsel = ((lane >> 3) & 1) * 4;
#pragma unroll
    for (int p = 0; p < 4; p++)
        o.b[p] = (uint32_t)((STAGE_F + (wn + p * 16 + lb) * TS + bsel) * 4);
    return o;
}

// ================  generic GEMM: C = A[M,K] @ W[N,K]^T + bias (+res) =======
// If A2 != null, A covers k<256 and A2 covers k>=256 (both row-stride 256).
template <bool RES>
__global__ void __launch_bounds__(256)
mma_gemm_kernel(const float* __restrict__ A, const float* __restrict__ A2,
                const float* __restrict__ W,
                const float* __restrict__ bias, const float* __restrict__ resid,
                float* __restrict__ C, int M, int N, int K, int lda) {
    extern __shared__ __align__(16) float sm[];
    const uint32_t sb = smem_u32(sm);
    const int tid  = threadIdx.x;
    const int wid  = tid >> 5;
    const int lane = tid & 31;
    const int g    = lane >> 2;
    const int t4   = lane & 3;
    const int bm = blockIdx.y * 128;
    const int bn = blockIdx.x * 128;
    const int wm = (wid & 3) * 32;
    const int wn = (wid >> 2) * 64;
    const int NT = K >> 5;
    const LdsmOffs offs = make_offs(lane, wm, wn);

    float acc[2][8][4];
#pragma unroll
    for (int i = 0; i < 2; i++)
#pragma unroll
        for (int j = 0; j < 8; j++)
#pragma unroll
            for (int c = 0; c < 4; c++) acc[i][j][c] = 0.f;

    auto ldstage = [&](int u) {
        const int slot = u % G_STAGES;
        const int k0 = u << 5;
        const float* srcA = A;
        int ka = k0;
        if (A2 != nullptr && k0 >= 256) { srcA = A2; ka = k0 - 256; }
        const uint32_t sbase = sb + (uint32_t)slot * G_STAGE_B;
#pragma unroll
        for (int i = 0; i < 4; i++) {
            const int idx = tid + i * 256;
            const int row = idx >> 3;
            const int ch  = idx & 7;
            cp_async16(sbase + (uint32_t)(row * TS + ch * 4) * 4,
                       srcA + (size_t)(bm + row) * lda + ka + ch * 4);
        }
#pragma unroll
        for (int i = 0; i < 4; i++) {
            const int idx = tid + i * 256;
            const int row = idx >> 3;
            const int ch  = idx & 7;
            cp_async16(sbase + (uint32_t)(STAGE_F + row * TS + ch * 4) * 4,
                       W + (size_t)(bn + row) * K + k0 + ch * 4);
        }
    };

    ldstage(0); CP_COMMIT();
    ldstage(1); CP_COMMIT();

    for (int t = 0; t < NT; t++) {
        CP_WAIT1();              // group t complete (t+1 may be pending)
        __syncthreads();         // all warps see stage t; slot t-1 free
        if (t + 2 < NT) ldstage(t + 2);
        CP_COMMIT();

        const uint32_t sbase = sb + (uint32_t)(t % G_STAGES) * G_STAGE_B;
#pragma unroll
        for (int kc = 0; kc < 4; kc++) {
            const uint32_t kbyte = kc * 32;
            uint32_t af0[4], af1[4];
            ldsm_x4(af0, sbase + offs.a0 + kbyte);
            ldsm_x4(af1, sbase + offs.a1 + kbyte);
#pragma unroll
            for (int p = 0; p < 4; p++) {
                uint32_t b4[4];
                ldsm_x4(b4, sbase + offs.b[p] + kbyte);
                mma_tf32(acc[0][2 * p],     af0, b4);
                mma_tf32(acc[1][2 * p],     af1, b4);
                mma_tf32(acc[0][2 * p + 1], af0, b4 + 2);
                mma_tf32(acc[1][2 * p + 1], af1, b4 + 2);
            }
        }
    }

#pragma unroll
    for (int nt = 0; nt < 8; nt++) {
        const int col = bn + wn + nt * 8 + t4 * 2;
        const float2 bv = *(const float2*)&bias[col];
#pragma unroll
        for (int mt = 0; mt < 2; mt++) {
            const int r0 = bm + wm + mt * 16 + g;
            float2 v0 = make_float2(acc[mt][nt][0] + bv.x, acc[mt][nt][1] + bv.y);
            float2 v1 = make_float2(acc[mt][nt][2] + bv.x, acc[mt][nt][3] + bv.y);
            if (RES) {
                const float2 r0v = *(const float2*)&resid[(size_t)r0 * N + col];
                const float2 r1v = *(const float2*)&resid[(size_t)(r0 + 8) * N + col];
                v0.x += r0v.x; v0.y += r0v.y;
                v1.x += r1v.x; v1.y += r1v.y;
            }
            *(float2*)&C[(size_t)r0 * N + col]       = v0;
            *(float2*)&C[(size_t)(r0 + 8) * N + col] = v1;
        }
    }
}

// ================  QKV GEMM + fused RoPE + split ===========================
// Canonical output col n' in [0,768): t=n'>>8 (0=q,1=k,2=v), h=(n'>>6)&3,
// d=n'&63. W rows permuted at load: src = h*192 + d*3 + t.
// q/k: RoPE'd, [B,H,S,Dh]; v: transposed store [B,H,Dh,S].
__global__ void __launch_bounds__(256)
qkv_gemm_rope_kernel(const float* __restrict__ A, const float* __restrict__ W,
                     const float* __restrict__ bias, const float* __restrict__ kp) {
    extern __shared__ __align__(16) float sm[];
    const uint32_t sb = smem_u32(sm);
    const int tid  = threadIdx.x;
    const int wid  = tid >> 5;
    const int lane = tid & 31;
    const int g    = lane >> 2;
    const int t4   = lane & 3;
    const int bm = blockIdx.y * 128;
    const int bn = blockIdx.x * 128;
    const int wm = (wid & 3) * 32;
    const int wn = (wid >> 2) * 64;
    const int NT = 8;                       // K = 256
    const LdsmOffs offs = make_offs(lane, wm, wn);

    float acc[2][8][4];
#pragma unroll
    for (int i = 0; i < 2; i++)
#pragma unroll
        for (int j = 0; j < 8; j++)
#pragma unroll
            for (int c = 0; c < 4; c++) acc[i][j][c] = 0.f;

    auto ldstage = [&](int u) {
        const int slot = u % G_STAGES;
        const int k0 = u << 5;
        const uint32_t sbase = sb + (uint32_t)slot * G_STAGE_B;
#pragma unroll
        for (int i = 0; i < 4; i++) {
            const int idx = tid + i * 256;
            const int row = idx >> 3;
            const int ch  = idx & 7;
            cp_async16(sbase + (uint32_t)(row * TS + ch * 4) * 4,
                       A + (size_t)(bm + row) * 256 + k0 + ch * 4);
        }
#pragma unroll
        for (int i = 0; i < 4; i++) {
            const int idx = tid + i * 256;
            const int row = idx >> 3;
            const int ch  = idx & 7;
            const int rp  = bn + row;              // canonical col
            const int tt  = rp >> 8;
            const int hh  = (rp >> 6) & 3;
            const int dd  = rp & 63;
            const int src = hh * 192 + dd * 3 + tt;
            cp_async16(sbase + (uint32_t)(STAGE_F + row * TS + ch * 4) * 4,
                       W + (size_t)src * 256 + k0 + ch * 4);
        }
    };

    ldstage(0); CP_COMMIT();
    ldstage(1); CP_COMMIT();

    for (int t = 0; t < NT; t++) {
        CP_WAIT1();
        __syncthreads();
        if (t + 2 < NT) ldstage(t + 2);
        CP_COMMIT();

        const uint32_t sbase = sb + (uint32_t)(t % G_STAGES) * G_STAGE_B;
#pragma unroll
        for (int kc = 0; kc < 4; kc++) {
            const uint32_t kbyte = kc * 32;
            uint32_t af0[4], af1[4];
            ldsm_x4(af0, sbase + offs.a0 + kbyte);
            ldsm_x4(af1, sbase + offs.a1 + kbyte);
#pragma unroll
            for (int p = 0; p < 4; p++) {
                uint32_t b4[4];
                ldsm_x4(b4, sbase + offs.b[p] + kbyte);
                mma_tf32(acc[0][2 * p],     af0, b4);
                mma_tf32(acc[1][2 * p],     af1, b4);
                mma_tf32(acc[0][2 * p + 1], af0, b4 + 2);
                mma_tf32(acc[1][2 * p + 1], af1, b4 + 2);
            }
        }
    }

    // ---- epilogue: bias + RoPE + scatter -----------------------------------
    const int type = bn >> 8;               // 0=q, 1=k, 2=v (uniform per CTA)
    const float qs = (type == 0) ? 0.125f : 1.0f;

#pragma unroll
    for (int nt = 0; nt < 8; nt++) {
        const int colp = bn + wn + nt * 8 + t4 * 2;   // canonical col (even)
        const int h = (colp >> 6) & 3;
        const int d = colp & 63;
        const float b0 = bias[h * 192 + d * 3 + type];
        const float b1 = bias[h * 192 + (d + 1) * 3 + type];
#pragma unroll
        for (int mt = 0; mt < 2; mt++) {
            const int mA = bm + wm + mt * 16 + g;
#pragma unroll
            for (int rr = 0; rr < 2; rr++) {
                const int m = mA + rr * 8;
                const float x0 = acc[mt][nt][rr * 2 + 0] + b0;
                const float x1 = acc[mt][nt][rr * 2 + 1] + b1;
                const int bb = m >> 11;
                const int ss = m & 2047;
                if (type == 2) {
                    // transposed V store: [B,H,Dh,S]
                    const size_t off = (((size_t)(bb * 4 + h)) * 64 + d) * 2048 + ss;
                    g_v[off]        = x0;
                    g_v[off + 2048] = x1;
                } else {
                    const float2 c2 = *(const float2*)&kp[(size_t)m * 64 + d];
                    const float2 s2 = *(const float2*)&kp[(size_t)Mq * 64 + (size_t)m * 64 + d];
                    const float o0 = (x0 * c2.x - x1 * s2.x) * qs;
                    const float o1 = (x1 * c2.y + x0 * s2.y) * qs;
                    float* dst = (type == 0) ? g_q : g_k;
                    const size_t off = (((size_t)(bb * 4 + h)) * 2048 + ss) * 64 + d;
                    *(float2*)&dst[off] = make_float2(o0, o1);
                }
            }
        }
    }
}

// ============== flash attention with m16n8k8 tf32 mma + ldmatrix ===========
// Q,K: [B,H,S,64]; V: [B,H,64,S] (d-major). ctx: [B,S,256].
// P routed through per-warp-private smem (STS C-frag -> ldmatrix A-frag).
#define ATT_KPAD 68
#define ATT_VPAD 68
#define ATT_PPAD 68
#define ATT_KSTG (64 * ATT_KPAD)
#define ATT_VSTG (64 * ATT_VPAD)
#define ATT_SMEM ((2 * ATT_KSTG + 2 * ATT_VSTG + 128 * ATT_PPAD) * 4)

__global__ void __launch_bounds__(256)
fa_mma_kernel(const float* __restrict__ Q, const float* __restrict__ K,
              const float* __restrict__ V, float* __restrict__ ctx) {
    extern __shared__ __align__(16) float sm[];
    float* Ks = sm;
    float* Vs = sm + 2 * ATT_KSTG;
    float* Ps = sm + 2 * ATT_KSTG + 2 * ATT_VSTG;
    const uint32_t sKu = smem_u32(Ks);
    const uint32_t sVu = smem_u32(Vs);
    const uint32_t sPu = smem_u32(Ps);

    const int tid = threadIdx.x, wid = tid >> 5, lane = tid & 31;
    const int g = lane >> 2, t4 = lane & 3;
    const int b = blockIdx.z, h = blockIdx.y, it = blockIdx.x;
    const size_t base = ((size_t)(b * Hq + h)) * Sq * Dh;

    // ldmatrix per-thread offsets (B-frag pattern) for K and V tiles
    const int lb   = (lane & 7) + ((lane >> 4) << 3);
    const int bsel = ((lane >> 3) & 1) * 4;
    uint32_t kmoff[4], vmoff[4];
#pragma unroll
    for (int p = 0; p < 4; p++) {
        kmoff[p] = (uint32_t)(((p * 16 + lb) * ATT_KPAD + bsel) * 4);
        vmoff[p] = (uint32_t)(((p * 16 + lb) * ATT_VPAD + bsel) * 4);
    }
    // P A-frag ldmatrix base (per-warp 16 rows)
    const uint32_t pfrag = sPu + (uint32_t)(((wid * 16 + (lane & 15)) * ATT_PPAD
                                             + (lane >> 4) * 4) * 4);
    // P C-frag store bases
    float* prow0 = Ps + (wid * 16 + g)     * ATT_PPAD + t4 * 2;
    float* prow1 = Ps + (wid * 16 + g + 8) * ATT_PPAD + t4 * 2;

    // ---- stage Q tile (128x64) into K region --------------------------------
    {
        const float* Qg = Q + base + (size_t)it * 128 * Dh;
#pragma unroll
        for (int i = 0; i < 8; i++) {
            const int idx = tid + i * 256;
            const int row = idx >> 4;
            const int ch  = idx & 15;
            cp_async16(sKu + (uint32_t)(row * ATT_KPAD + ch * 4) * 4,
                       Qg + row * 64 + ch * 4);
        }
    }
    CP_COMMIT(); CP_WAIT0();
    __syncthreads();

    // Q A-frags via ldmatrix
    uint32_t aq[8][4];
    {
        const uint32_t qoff = (uint32_t)(((wid * 16 + (lane & 15)) * ATT_KPAD
                                          + (lane >> 4) * 4) * 4);
#pragma unroll
        for (int kb = 0; kb < 8; kb++)
            ldsm_x4(aq[kb], sKu + qoff + kb * 32);
    }
    __syncthreads();

    const float* Kg = K + base;
    const float* Vg = V + base;    // [64][2048]
    auto ldkv = [&](int jt) {
        const int slot = jt & 1;
#pragma unroll
        for (int i = 0; i < 4; i++) {
            const int idx = tid + i * 256;
            const int row = idx >> 4;
            const int ch  = idx & 15;
            cp_async16(sKu + (uint32_t)(slot * ATT_KSTG + row * ATT_KPAD + ch * 4) * 4,
                       Kg + (size_t)(jt * 64 + row) * 64 + ch * 4);
            cp_async16(sVu + (uint32_t)(slot * ATT_VSTG + row * ATT_VPAD + ch * 4) * 4,
                       Vg + (size_t)row * Sq + jt * 64 + ch * 4);
        }
    };

    ldkv(0); CP_COMMIT();

    float m0 = -INFINITY, m1 = -INFINITY, l0 = 0.f, l1 = 0.f;
    float o[8][4];
#pragma unroll
    for (int nt = 0; nt < 8; nt++)
#pragma unroll
        for (int c = 0; c < 4; c++) o[nt][c] = 0.f;

    for (int jt = 0; jt < Sq / 64; jt++) {
        if (jt + 1 < Sq / 64) { ldkv(jt + 1); CP_COMMIT(); CP_WAIT1(); }
        else                  { CP_WAIT0(); }
        __syncthreads();

        const uint32_t kbase = sKu + (uint32_t)((jt & 1) * ATT_KSTG) * 4;
        const uint32_t vbase = sVu + (uint32_t)((jt & 1) * ATT_VSTG) * 4;

        // ---- S = Q K^T -----------------------------------------------------
        float sc[8][4];
#pragma unroll
        for (int nt = 0; nt < 8; nt++)
#pragma unroll
            for (int c = 0; c < 4; c++) sc[nt][c] = 0.f;
#pragma unroll
        for (int kb = 0; kb < 8; kb++) {
            const uint32_t kbyte = kb * 32;
#pragma unroll
            for (int p = 0; p < 4; p++) {
                uint32_t b4[4];
                ldsm_x4(b4, kbase + kmoff[p] + kbyte);
                mma_tf32(sc[2 * p],     aq[kb], b4);
                mma_tf32(sc[2 * p + 1], aq[kb], b4 + 2);
            }
        }

        // ---- online softmax ------------------------------------------------
        float mx0 = -INFINITY, mx1 = -INFINITY;
#pragma unroll
        for (int nt = 0; nt < 8; nt++) {
            mx0 = fmaxf(mx0, fmaxf(sc[nt][0], sc[nt][1]));
            mx1 = fmaxf(mx1, fmaxf(sc[nt][2], sc[nt][3]));
        }
        mx0 = fmaxf(mx0, __shfl_xor_sync(0xffffffffu, mx0, 1));
        mx0 = fmaxf(mx0, __shfl_xor_sync(0xffffffffu, mx0, 2));
        mx1 = fmaxf(mx1, __shfl_xor_sync(0xffffffffu, mx1, 1));
        mx1 = fmaxf(mx1, __shfl_xor_sync(0xffffffffu, mx1, 2));

        const float nm0 = fmaxf(m0, mx0);
        const float nm1 = fmaxf(m1, mx1);
        const float f0 = __expf(m0 - nm0);
        const float f1 = __expf(m1 - nm1);
        float sum0 = 0.f, sum1 = 0.f;
#pragma unroll
        for (int nt = 0; nt < 8; nt++) {
            sc[nt][0] = __expf(sc[nt][0] - nm0);
            sc[nt][1] = __expf(sc[nt][1] - nm0);
            sc[nt][2] = __expf(sc[nt][2] - nm1);
            sc[nt][3] = __expf(sc[nt][3] - nm1);
            sum0 += sc[nt][0] + sc[nt][1];
            sum1 += sc[nt][2] + sc[nt][3];
        }
        sum0 += __shfl_xor_sync(0xffffffffu, sum0, 1);
        sum0 += __shfl_xor_sync(0xffffffffu, sum0, 2);
        sum1 += __shfl_xor_sync(0xffffffffu, sum1, 1);
        sum1 += __shfl_xor_sync(0xffffffffu, sum1, 2);
        l0 = l0 * f0 + sum0;
        l1 = l1 * f1 + sum1;
        m0 = nm0; m1 = nm1;
#pragma unroll
        for (int nt = 0; nt < 8; nt++) {
            o[nt][0] *= f0; o[nt][1] *= f0;
            o[nt][2] *= f1; o[nt][3] *= f1;
        }

        // ---- P: C-frag -> smem -> A-frag (per-warp private tile) ----------
#pragma unroll
        for (int nt = 0; nt < 8; nt++) {
            *(float2*)&prow0[nt * 8] = make_float2(sc[nt][0], sc[nt][1]);
            *(float2*)&prow1[nt * 8] = make_float2(sc[nt][2], sc[nt][3]);
        }
        __syncwarp();

        // ---- O += P V  -----------------------------------------------------
#pragma unroll
        for (int kb = 0; kb < 8; kb++) {
            uint32_t ap[4];
            ldsm_x4(ap, pfrag + kb * 32);
            const uint32_t jbyte = kb * 32;
#pragma unroll
            for (int p = 0; p < 4; p++) {
                uint32_t b4[4];
                ldsm_x4(b4, vbase + vmoff[p] + jbyte);
                mma_tf32(o[2 * p],     ap, b4);
                mma_tf32(o[2 * p + 1], ap, b4 + 2);
            }
        }
        __syncthreads();
    }

    const float il0 = 1.f / l0;
    const float il1 = 1.f / l1;
    const int row0 = it * 128 + wid * 16 + g;
#pragma unroll
    for (int nt = 0; nt < 8; nt++) {
        const int col = h * Dh + nt * 8 + t4 * 2;
        float2 v0 = make_float2(o[nt][0] * il0, o[nt][1] * il0);
        float2 v1 = make_float2(o[nt][2] * il1, o[nt][3] * il1);
        *(float2*)&ctx[((size_t)b * Sq + row0) * Dq + col]     = v0;
        *(float2*)&ctx[((size_t)b * Sq + row0 + 8) * Dq + col] = v1;
    }
}

// ---------------- LayerNorm(512) + exact GELU, warp per row ----------------
__global__ void __launch_bounds__(256)
ln_gelu_kernel(const float* __restrict__ gamma, const float* __restrict__ beta) {
    const int lane = threadIdx.x & 31;
    const int row  = blockIdx.x * 8 + (threadIdx.x >> 5);
    float* rp = g_y + (size_t)row * 512;

    float4 x[4];
    float s = 0.f, ss = 0.f;
#pragma unroll
    for (int j = 0; j < 4; j++) {
        x[j] = *(const float4*)&rp[lane * 4 + j * 128];
        s  += x[j].x + x[j].y + x[j].z + x[j].w;
        ss += x[j].x * x[j].x + x[j].y * x[j].y + x[j].z * x[j].z + x[j].w * x[j].w;
    }
#pragma unroll
    for (int msk = 16; msk >= 1; msk >>= 1) {
        s  += __shfl_xor_sync(0xffffffffu, s,  msk);
        ss += __shfl_xor_sync(0xffffffffu, ss, msk);
    }
    const float mu  = s * (1.f / 512.f);
    const float var = ss * (1.f / 512.f) - mu * mu;
    const float inv = rsqrtf(var + 1e-5f);

#pragma unroll
    for (int j = 0; j < 4; j++) {
        const int c = lane * 4 + j * 128;
        const float4 gm = *(const float4*)&gamma[c];
        const float4 bt = *(const float4*)&beta[c];
        float4 y;
        y.x = (x[j].x - mu) * inv * gm.x + bt.x;
        y.y = (x[j].y - mu) * inv * gm.y + bt.y;
        y.z = (x[j].z - mu) * inv * gm.z + bt.z;
        y.w = (x[j].w - mu) * inv * gm.w + bt.w;
        y.x = 0.5f * y.x * (1.f + erff(y.x * 0.70710678118654752440f));
        y.y = 0.5f * y.y * (1.f + erff(y.y * 0.70710678118654752440f));
        y.z = 0.5f * y.z * (1.f + erff(y.z * 0.70710678118654752440f));
        y.w = 0.5f * y.w * (1.f + erff(y.w * 0.70710678118654752440f));
        *(float4*)&rp[c] = y;
    }
}

// ---------------- launch ----------------------------------------------------
extern "C" void kernel_launch(void* const* d_in, const int* in_sizes, int n_in,
                              void* d_out, int out_size) {
    const float* desc   = (const float*)d_in[0];
    const float* kp     = (const float*)d_in[1];
    const float* Wqkv_w = (const float*)d_in[2];
    const float* Wqkv_b = (const float*)d_in[3];
    const float* Wo_w   = (const float*)d_in[4];
    const float* Wo_b   = (const float*)d_in[5];
    const float* W1_w   = (const float*)d_in[6];
    const float* W1_b   = (const float*)d_in[7];
    const float* ln_g   = (const float*)d_in[8];
    const float* ln_b   = (const float*)d_in[9];
    const float* W2_w   = (const float*)d_in[10];
    const float* W2_b   = (const float*)d_in[11];
    float* out = (float*)d_out;

    void *p_q, *p_k, *p_v, *p_ctx, *p_msg, *p_y;
    cudaGetSymbolAddress(&p_q,   g_q);
    cudaGetSymbolAddress(&p_k,   g_k);
    cudaGetSymbolAddress(&p_v,   g_v);
    cudaGetSymbolAddress(&p_ctx, g_ctx);
    cudaGetSymbolAddress(&p_msg, g_msg);
    cudaGetSymbolAddress(&p_y,   g_y);

    cudaFuncSetAttribute(qkv_gemm_rope_kernel,
                         cudaFuncAttributeMaxDynamicSharedMemorySize, G_SMEM_TOT);
    cudaFuncSetAttribute(mma_gemm_kernel<false>,
                         cudaFuncAttributeMaxDynamicSharedMemorySize, G_SMEM_TOT);
    cudaFuncSetAttribute(mma_gemm_kernel<true>,
                         cudaFuncAttributeMaxDynamicSharedMemorySize, G_SMEM_TOT);
    cudaFuncSetAttribute(fa_mma_kernel,
                         cudaFuncAttributeMaxDynamicSharedMemorySize, ATT_SMEM);

    // 1) QKV GEMM + RoPE + split -> g_q/g_k (S-major), g_v (Dh-major)
    qkv_gemm_rope_kernel<<<dim3(6, Mq / 128), 256, G_SMEM_TOT>>>(
        desc, Wqkv_w, Wqkv_b, kp);

    // 2) flash attention (tensor-core, ldmatrix) -> ctx [B,S,D]
    fa_mma_kernel<<<dim3(Sq / 128, Hq, Bq), 256, ATT_SMEM>>>(
        (const float*)p_q, (const float*)p_k, (const float*)p_v, (float*)p_ctx);

    // 3) message = ctx @ Wo^T + b
    mma_gemm_kernel<false><<<dim3(Dq / 128, Mq / 128), 256, G_SMEM_TOT>>>(
        (const float*)p_ctx, nullptr, Wo_w, Wo_b, nullptr,
        (float*)p_msg, Mq, Dq, Dq, Dq);

    // 4) y = [desc | msg] @ W1^T + b   (virtual concat via split-K loader)
    mma_gemm_kernel<false><<<dim3(512 / 128, Mq / 128), 256, G_SMEM_TOT>>>(
        desc, (const float*)p_msg, W1_w, W1_b, nullptr,
        (float*)p_y, Mq, 512, 512, 256);

    // 5) LayerNorm + GELU (in place, warp per row)
    ln_gelu_kernel<<<Mq / 8, 256>>>(ln_g, ln_b);

    // 6) out = desc + y @ W2^T + b
    mma_gemm_kernel<true><<<dim3(Dq / 128, Mq / 128), 256, G_SMEM_TOT>>>(
        (const float*)p_y, nullptr, W2_w, W2_b, desc, out, Mq, Dq, 512, 512);
}